// round 2
// baseline (speedup 1.0000x reference)
#include <cuda_runtime.h>
#include <cuda_bf16.h>
#include <cstdint>

// ---------------------------------------------------------------------------
// Problem constants
// ---------------------------------------------------------------------------
#define B_   4
#define T_   1024
#define C_   2048
#define NH   16
#define NKV  4
#define HD   128
#define M_   (B_ * T_)            // 4096 rows
#define QDIM (NH * HD)            // 2048
#define KDIM (NKV * HD)           // 512

// Scratch (device globals; no allocation allowed)
__device__ float g_q [M_ * QDIM];   // 32 MB
__device__ float g_k [M_ * KDIM];   // 8 MB
__device__ float g_v [M_ * KDIM];   // 8 MB
__device__ float g_ao[M_ * QDIM];   // 32 MB

// ---------------------------------------------------------------------------
// f32x2 packed-FMA helpers (sm_100a): 2x fp32 FMA throughput vs FFMA-3reg
// ---------------------------------------------------------------------------
typedef unsigned long long ull;

__device__ __forceinline__ ull pk2(float x, float y) {
    ull r;
    asm("mov.b64 %0, {%1, %2};" : "=l"(r) : "f"(x), "f"(y));
    return r;
}
__device__ __forceinline__ void fma2(ull& c, ull a, ull b) {
    asm("fma.rn.f32x2 %0, %1, %2, %0;" : "+l"(c) : "l"(a), "l"(b));
}
__device__ __forceinline__ void mul2(ull& c, ull a) {
    asm("mul.rn.f32x2 %0, %0, %1;" : "+l"(c) : "l"(a));
}
__device__ __forceinline__ float2 upk(ull v) {
    float2 r;
    asm("mov.b64 {%0, %1}, %2;" : "=f"(r.x), "=f"(r.y) : "l"(v));
    return r;
}

// ---------------------------------------------------------------------------
// GEMM: C[M,N] = A[M,K] @ B[K,N], all fp32 row-major.
// 128x128 tile, BK=8, 256 threads, 8x8 per thread (split-tile mapping),
// f32x2 packed accumulators, register-prefetched global loads.
// Requires M%128==0, N%128==0, K%8==0 (holds for all our shapes).
// ---------------------------------------------------------------------------
__global__ void __launch_bounds__(256, 2)
gemm128(const float* __restrict__ A, const float* __restrict__ Bm,
        float* __restrict__ C, int M, int N, int K)
{
    __shared__ float As[8][128];   // transposed: As[k][m]
    __shared__ float Bs[8][128];   // Bs[k][n]

    const int tid = threadIdx.x;
    const int tx  = tid & 15;      // 0..15  -> N
    const int ty  = tid >> 4;      // 0..15  -> M
    const int bm  = blockIdx.y * 128;
    const int bn  = blockIdx.x * 128;

    // Global load assignments
    const int ra  = tid >> 1;           // A tile row   0..127
    const int ka  = (tid & 1) * 4;      // A tile k-col 0 or 4
    const int kb  = tid >> 5;           // B tile k-row 0..7
    const int cb  = (tid & 31) * 4;     // B tile col   0..124

    const float* Abase = A  + (size_t)(bm + ra) * K + ka;
    const float* Bbase = Bm + (size_t)kb * N + bn + cb;

    ull acc[8][4];
    #pragma unroll
    for (int i = 0; i < 8; ++i)
        #pragma unroll
        for (int j = 0; j < 4; ++j) acc[i][j] = 0ull;

    float4 pa = *(const float4*)(Abase);
    float4 pb = *(const float4*)(Bbase);

    for (int k0 = 0; k0 < K; k0 += 8) {
        __syncthreads();   // prior-iteration readers done before overwrite
        // stage tile to smem (A transposed)
        As[ka + 0][ra] = pa.x;
        As[ka + 1][ra] = pa.y;
        As[ka + 2][ra] = pa.z;
        As[ka + 3][ra] = pa.w;
        *(float4*)&Bs[kb][cb] = pb;
        __syncthreads();

        if (k0 + 8 < K) {
            pa = *(const float4*)(Abase + (k0 + 8));
            pb = *(const float4*)(Bbase + (size_t)(k0 + 8) * N);
        }

        #pragma unroll
        for (int kk = 0; kk < 8; ++kk) {
            float4 a0 = *(const float4*)&As[kk][ty * 4];
            float4 a1 = *(const float4*)&As[kk][64 + ty * 4];
            ulonglong2 bl0 = *(const ulonglong2*)&Bs[kk][tx * 4];
            ulonglong2 bl1 = *(const ulonglong2*)&Bs[kk][64 + tx * 4];
            ull b2[4] = {bl0.x, bl0.y, bl1.x, bl1.y};
            float af[8] = {a0.x, a0.y, a0.z, a0.w, a1.x, a1.y, a1.z, a1.w};
            #pragma unroll
            for (int i = 0; i < 8; ++i) {
                ull a2 = pk2(af[i], af[i]);
                #pragma unroll
                for (int j = 0; j < 4; ++j) fma2(acc[i][j], a2, b2[j]);
            }
        }
    }

    // writeback
    #pragma unroll
    for (int i = 0; i < 8; ++i) {
        int row = bm + ((i < 4) ? (ty * 4 + i) : (64 + ty * 4 + (i - 4)));
        float* crow = C + (size_t)row * N;
        float2 c0 = upk(acc[i][0]), c1 = upk(acc[i][1]);
        float2 c2 = upk(acc[i][2]), c3 = upk(acc[i][3]);
        float4 w0 = make_float4(c0.x, c0.y, c1.x, c1.y);
        float4 w1 = make_float4(c2.x, c2.y, c3.x, c3.y);
        *(float4*)&crow[bn + tx * 4]      = w0;
        *(float4*)&crow[bn + 64 + tx * 4] = w1;
    }
}

// ---------------------------------------------------------------------------
// Fused RoPE + RMSNorm over one head-row of 128 (applied to q and k).
// grid: (B*T, NH + NKV), block: 64 threads (each handles rotation pair i,i+64)
// ---------------------------------------------------------------------------
__global__ void rope_rms_kernel(float* __restrict__ q, float* __restrict__ k,
                                const float* __restrict__ cosp,
                                const float* __restrict__ sinp)
{
    const int bt = blockIdx.x;           // b*T + t
    const int h  = blockIdx.y;           // 0..15 q-head, 16..19 k-head
    const int t  = bt & (T_ - 1);
    const int i  = threadIdx.x;          // 0..63

    float* row = (h < NH)
        ? (q + (size_t)bt * QDIM + h * HD)
        : (k + (size_t)bt * KDIM + (h - NH) * HD);

    float x1 = row[i];
    float x2 = row[i + 64];
    float c  = cosp[t * 64 + i];
    float s  = sinp[t * 64 + i];
    float y1 = x1 * c - x2 * s;
    float y2 = x1 * s + x2 * c;

    float ss = y1 * y1 + y2 * y2;
    #pragma unroll
    for (int off = 16; off > 0; off >>= 1)
        ss += __shfl_xor_sync(0xffffffffu, ss, off);

    __shared__ float wsum[2];
    if ((i & 31) == 0) wsum[i >> 5] = ss;
    __syncthreads();
    float tot = wsum[0] + wsum[1];
    float rn  = rsqrtf(tot * (1.0f / 128.0f) + 1e-6f);

    row[i]      = y1 * rn;
    row[i + 64] = y2 * rn;
}

// ---------------------------------------------------------------------------
// Flash attention (causal, GQA 4:1), fp32, online softmax.
// BM=BN=64, D=128. One CTA per (q-tile, head, batch). 256 threads.
// Inner loops use packed fma.rn.f32x2 (QK^T packs over the contraction dim;
// PV packs over contiguous output-column pairs).
// ---------------------------------------------------------------------------
struct AttnSmem {
    float Q[64][132];
    float K[64][132];
    float V[64][132];
    float P[64][68];
    float m[64];
    float l[64];
    float al[64];
};

extern __shared__ char attn_smem_raw[];

__global__ void __launch_bounds__(256)
attn_kernel(const float* __restrict__ q, const float* __restrict__ k,
            const float* __restrict__ v, float* __restrict__ o)
{
    AttnSmem& S = *reinterpret_cast<AttnSmem*>(attn_smem_raw);
    const int qt  = blockIdx.x;          // 0..15 q tile
    const int h   = blockIdx.y;          // 0..15
    const int b   = blockIdx.z;          // 0..3
    const int kvh = h >> 2;
    const int tid = threadIdx.x;
    const int tx  = tid & 15;
    const int ty  = tid >> 4;

    const int r0 = tid >> 5;             // 0..7
    const int d4 = (tid & 31) * 4;       // 0..124

    // Load Q tile (64x128)
    const float* qbase = q + (size_t)(b * T_ + qt * 64) * QDIM + h * HD;
    #pragma unroll
    for (int it = 0; it < 8; ++it) {
        int r = r0 + it * 8;
        *(float4*)&S.Q[r][d4] = *(const float4*)(qbase + (size_t)r * QDIM + d4);
    }
    if (tid < 64) { S.m[tid] = -1e30f; S.l[tid] = 0.0f; }

    // O accumulators: rows ty+16i, column pairs (tx*2 + 32*j, +1)
    ull oacc2[4][4];
    #pragma unroll
    for (int i = 0; i < 4; ++i)
        #pragma unroll
        for (int j = 0; j < 4; ++j) oacc2[i][j] = 0ull;

    const float scale = 0.08838834764831845f;   // 1/sqrt(128)

    for (int kt = 0; kt <= qt; ++kt) {
        __syncthreads();   // previous PV readers done; Q stores covered too
        const float* kbase = k + (size_t)(b * T_ + kt * 64) * KDIM + kvh * HD;
        const float* vbase = v + (size_t)(b * T_ + kt * 64) * KDIM + kvh * HD;
        #pragma unroll
        for (int it = 0; it < 8; ++it) {
            int r = r0 + it * 8;
            *(float4*)&S.K[r][d4] = *(const float4*)(kbase + (size_t)r * KDIM + d4);
            *(float4*)&S.V[r][d4] = *(const float4*)(vbase + (size_t)r * KDIM + d4);
        }
        __syncthreads();

        // S = Q K^T (64x64), 4x4 per thread; packed over contraction dim.
        ull sacc2[4][4];
        #pragma unroll
        for (int i = 0; i < 4; ++i)
            #pragma unroll
            for (int j = 0; j < 4; ++j) sacc2[i][j] = 0ull;

        #pragma unroll 8
        for (int kk = 0; kk < 128; kk += 2) {
            ull qf2[4], kf2[4];
            #pragma unroll
            for (int i = 0; i < 4; ++i)
                qf2[i] = *(const ull*)&S.Q[ty + 16 * i][kk];
            #pragma unroll
            for (int j = 0; j < 4; ++j)
                kf2[j] = *(const ull*)&S.K[tx + 16 * j][kk];
            #pragma unroll
            for (int i = 0; i < 4; ++i)
                #pragma unroll
                for (int j = 0; j < 4; ++j)
                    fma2(sacc2[i][j], qf2[i], kf2[j]);
        }

        // scale, causal mask (diagonal tile only), store to shared
        const bool diag = (kt == qt);
        #pragma unroll
        for (int i = 0; i < 4; ++i) {
            int rr = ty + 16 * i;
            #pragma unroll
            for (int j = 0; j < 4; ++j) {
                int cc = tx + 16 * j;
                float2 sp = upk(sacc2[i][j]);
                float sv = (sp.x + sp.y) * scale;
                if (diag && cc > rr) sv = -1e30f;
                S.P[rr][cc] = sv;
            }
        }
        __syncthreads();

        // online softmax: 4 lanes per row
        {
            int row = tid >> 2, qq = tid & 3;
            float mloc = -1e30f;
            #pragma unroll
            for (int c = 0; c < 16; ++c)
                mloc = fmaxf(mloc, S.P[row][qq * 16 + c]);
            mloc = fmaxf(mloc, __shfl_xor_sync(0xffffffffu, mloc, 1));
            mloc = fmaxf(mloc, __shfl_xor_sync(0xffffffffu, mloc, 2));
            float mo = S.m[row];
            float mn = fmaxf(mo, mloc);
            float sum = 0.0f;
            #pragma unroll
            for (int c = 0; c < 16; ++c) {
                int idx = qq * 16 + c;
                float p = __expf(S.P[row][idx] - mn);
                S.P[row][idx] = p;
                sum += p;
            }
            sum += __shfl_xor_sync(0xffffffffu, sum, 1);
            sum += __shfl_xor_sync(0xffffffffu, sum, 2);
            if (qq == 0) {
                float a = __expf(mo - mn);
                S.al[row] = a;
                S.l[row]  = S.l[row] * a + sum;
                S.m[row]  = mn;
            }
        }
        __syncthreads();

        // rescale O, then O += P @ V (packed column pairs)
        #pragma unroll
        for (int i = 0; i < 4; ++i) {
            float a = S.al[ty + 16 * i];
            ull a2 = pk2(a, a);
            #pragma unroll
            for (int j = 0; j < 4; ++j) mul2(oacc2[i][j], a2);
        }

        #pragma unroll 4
        for (int kc = 0; kc < 64; ++kc) {
            ull pv2[4], vv2[4];
            #pragma unroll
            for (int i = 0; i < 4; ++i) {
                float p = S.P[ty + 16 * i][kc];
                pv2[i] = pk2(p, p);
            }
            #pragma unroll
            for (int j = 0; j < 4; ++j)
                vv2[j] = *(const ull*)&S.V[kc][tx * 2 + 32 * j];
            #pragma unroll
            for (int i = 0; i < 4; ++i)
                #pragma unroll
                for (int j = 0; j < 4; ++j)
                    fma2(oacc2[i][j], pv2[i], vv2[j]);
        }
    }

    // final normalize + write (column pairs tx*2 + 32*j)
    #pragma unroll
    for (int i = 0; i < 4; ++i) {
        int r = ty + 16 * i;
        float inv = 1.0f / S.l[r];
        size_t rowoff = (size_t)(b * T_ + qt * 64 + r) * QDIM + h * HD;
        #pragma unroll
        for (int j = 0; j < 4; ++j) {
            float2 c = upk(oacc2[i][j]);
            *(float2*)&o[rowoff + tx * 2 + 32 * j] =
                make_float2(c.x * inv, c.y * inv);
        }
    }
}

// ---------------------------------------------------------------------------
// Launch
// ---------------------------------------------------------------------------
extern "C" void kernel_launch(void* const* d_in, const int* in_sizes, int n_in,
                              void* d_out, int out_size)
{
    const float* x    = (const float*)d_in[0];
    const float* cosp = (const float*)d_in[1];
    const float* sinp = (const float*)d_in[2];
    const float* Wq   = (const float*)d_in[3];
    const float* Wk   = (const float*)d_in[4];
    const float* Wv   = (const float*)d_in[5];
    const float* Wo   = (const float*)d_in[6];
    float* out        = (float*)d_out;

    float *qb, *kb, *vb, *aob;
    cudaGetSymbolAddress((void**)&qb,  g_q);
    cudaGetSymbolAddress((void**)&kb,  g_k);
    cudaGetSymbolAddress((void**)&vb,  g_v);
    cudaGetSymbolAddress((void**)&aob, g_ao);

    cudaFuncSetAttribute(attn_kernel,
                         cudaFuncAttributeMaxDynamicSharedMemorySize,
                         (int)sizeof(AttnSmem));

    dim3 gq(QDIM / 128, M_ / 128);   // 16 x 32
    dim3 gk(KDIM / 128, M_ / 128);   // 4 x 32

    gemm128<<<gq, 256>>>(x, Wq, qb, M_, QDIM, C_);
    gemm128<<<gk, 256>>>(x, Wk, kb, M_, KDIM, C_);
    gemm128<<<gk, 256>>>(x, Wv, vb, M_, KDIM, C_);

    rope_rms_kernel<<<dim3(M_, NH + NKV), 64>>>(qb, kb, cosp, sinp);

    attn_kernel<<<dim3(T_ / 64, NH, B_), 256, sizeof(AttnSmem)>>>(qb, kb, vb, aob);

    gemm128<<<gq, 256>>>(aob, Wo, out, M_, QDIM, C_);
}